// round 1
// baseline (speedup 1.0000x reference)
#include <cuda_runtime.h>
#include <cuda_bf16.h>
#include <math.h>
#include <float.h>

// Problem constants (shapes are fixed by the dataset)
#define E_EDGES   1600000
#define N_NODES   50000
#define D_IN      128
#define D_OUT     128
#define K_GEMM    512          // 4 stats * 128
#define EPS_STD   1e-5f
#define EPS_BN    1e-5f

#define SCAN_BLK  256
#define SCAN_NBLK ((N_NODES + SCAN_BLK - 1) / SCAN_BLK)   // 196

// ------------------------- device scratch (no mallocs allowed) -----------
__device__ int   g_counts[N_NODES];
__device__ int   g_offsets[N_NODES + 1];
__device__ int   g_cursor[N_NODES];
__device__ int   g_deg[N_NODES];
__device__ int   g_perm[E_EDGES];
__device__ int   g_blocksums[SCAN_NBLK];
__device__ float g_x[(size_t)N_NODES * K_GEMM];      // [N, 512] aggregated features
__device__ float g_degW[100 * D_OUT];                // deg_emb @ W[512:640]
__device__ float g_colsum[D_OUT];
__device__ float g_colsq[D_OUT];
__device__ float g_scale[D_OUT];
__device__ float g_bias[D_OUT];

// ------------------------- init ------------------------------------------
__global__ void k_zeroinit() {
    int i = blockIdx.x * blockDim.x + threadIdx.x;
    if (i < N_NODES) g_counts[i] = 0;
    if (i < D_OUT) { g_colsum[i] = 0.f; g_colsq[i] = 0.f; }
}

// ------------------------- histogram -------------------------------------
__global__ void k_hist(const int* __restrict__ index) {
    int i = blockIdx.x * blockDim.x + threadIdx.x;
    if (i < E_EDGES) atomicAdd(&g_counts[index[i]], 1);
}

// ------------------------- scan (3 phases) --------------------------------
__global__ void k_scan1() {
    __shared__ int sm[SCAN_BLK];
    int i = blockIdx.x * SCAN_BLK + threadIdx.x;
    sm[threadIdx.x] = (i < N_NODES) ? g_counts[i] : 0;
    __syncthreads();
    for (int off = SCAN_BLK / 2; off > 0; off >>= 1) {
        if (threadIdx.x < off) sm[threadIdx.x] += sm[threadIdx.x + off];
        __syncthreads();
    }
    if (threadIdx.x == 0) g_blocksums[blockIdx.x] = sm[0];
}

__global__ void k_scan2() {   // single block, 256 threads; exclusive scan of blocksums
    __shared__ int sm[2][SCAN_BLK];
    int t = threadIdx.x;
    int v = (t < SCAN_NBLK) ? g_blocksums[t] : 0;
    sm[0][t] = v;
    __syncthreads();
    int pin = 0;
    for (int off = 1; off < SCAN_BLK; off <<= 1) {
        int nv = sm[pin][t] + ((t >= off) ? sm[pin][t - off] : 0);
        sm[pin ^ 1][t] = nv;
        __syncthreads();
        pin ^= 1;
    }
    if (t < SCAN_NBLK) g_blocksums[t] = sm[pin][t] - v;  // exclusive
}

__global__ void k_scan3() {
    __shared__ int sm[2][SCAN_BLK];
    int t = threadIdx.x;
    int i = blockIdx.x * SCAN_BLK + t;
    int v = (i < N_NODES) ? g_counts[i] : 0;
    sm[0][t] = v;
    __syncthreads();
    int pin = 0;
    for (int off = 1; off < SCAN_BLK; off <<= 1) {
        int nv = sm[pin][t] + ((t >= off) ? sm[pin][t - off] : 0);
        sm[pin ^ 1][t] = nv;
        __syncthreads();
        pin ^= 1;
    }
    int exc = sm[pin][t] - v;
    int base = g_blocksums[blockIdx.x];
    if (i < N_NODES) {
        g_offsets[i] = base + exc;
        g_cursor[i]  = base + exc;
    }
    if (i == 0) g_offsets[N_NODES] = E_EDGES;
}

// ------------------------- scatter (build perm) ---------------------------
__global__ void k_scatter(const int* __restrict__ index) {
    int i = blockIdx.x * blockDim.x + threadIdx.x;
    if (i < E_EDGES) {
        int n = index[i];
        int p = atomicAdd(&g_cursor[n], 1);
        g_perm[p] = i;
    }
}

// ------------------------- per-node aggregation ---------------------------
// one block (128 threads) per node; thread t owns feature dim t
__global__ __launch_bounds__(128) void k_agg(const float* __restrict__ inputs) {
    int n = blockIdx.x;
    int t = threadIdx.x;
    int start = g_offsets[n];
    int end   = g_offsets[n + 1];
    int cnt   = end - start;

    __shared__ int sperm[128];
    float s = 0.f, sq = 0.f;
    float mn = FLT_MAX, mx = -FLT_MAX;

    for (int base = start; base < end; base += 128) {
        int m = min(128, end - base);
        if (t < m) sperm[t] = g_perm[base + t];
        __syncthreads();
        #pragma unroll 4
        for (int j = 0; j < m; j++) {
            float v = __ldg(&inputs[(size_t)sperm[j] * D_IN + t]);
            s  += v;
            sq  = fmaf(v, v, sq);
            mn  = fminf(mn, v);
            mx  = fmaxf(mx, v);
        }
        __syncthreads();
    }

    float safe   = fmaxf((float)cnt, 1.f);
    float mean   = s / safe;
    float meansq = sq / safe;
    float stdv   = sqrtf(fmaxf(meansq - mean * mean, 0.f) + EPS_STD);
    if (cnt == 0) { mn = 0.f; mx = 0.f; }

    float* xr = g_x + (size_t)n * K_GEMM;
    xr[t]        = mean;
    xr[128 + t]  = mn;
    xr[256 + t]  = mx;
    xr[384 + t]  = stdv;
    if (t == 0) g_deg[n] = min(cnt, 99);
}

// ------------------------- degW = deg_emb @ W[512:640] --------------------
__global__ void k_degw(const float* __restrict__ deg_emb, const float* __restrict__ W) {
    int d = blockIdx.x;      // 0..99
    int o = threadIdx.x;     // 0..127
    __shared__ float e[D_IN];
    e[o] = deg_emb[d * D_IN + o];
    __syncthreads();
    float acc = 0.f;
    #pragma unroll 8
    for (int k = 0; k < D_IN; k++)
        acc = fmaf(e[k], W[(size_t)(K_GEMM + k) * D_OUT + o], acc);
    g_degW[d * D_OUT + o] = acc;
}

// ------------------------- GEMM: h = x[50000,512] @ W[512,128] + degW -----
#define BM 128
#define BN 128
#define BK 16
__global__ __launch_bounds__(256) void k_gemm(const float* __restrict__ W,
                                              float* __restrict__ out) {
    __shared__ float As[BK][BM + 4];   // transposed A tile, padded
    __shared__ float Bs[BK][BN];

    int tid = threadIdx.x;
    int bm  = blockIdx.x * BM;
    int tx  = tid & 15;     // col group 0..15  -> cols tx*8..tx*8+7
    int ty  = tid >> 4;     // row group 0..15  -> rows ty*8..ty*8+7

    float acc[8][8];
    #pragma unroll
    for (int i = 0; i < 8; i++)
        #pragma unroll
        for (int j = 0; j < 8; j++) acc[i][j] = 0.f;

    const float* A = g_x;

    for (int k0 = 0; k0 < K_GEMM; k0 += BK) {
        // load A tile: 128x16 floats = 512 float4; 2 per thread
        #pragma unroll
        for (int l = 0; l < 2; l++) {
            int f  = tid + l * 256;
            int m  = f >> 2;            // 0..127
            int kk = (f & 3) * 4;
            float4 v = make_float4(0.f, 0.f, 0.f, 0.f);
            int gm = bm + m;
            if (gm < N_NODES)
                v = *(const float4*)&A[(size_t)gm * K_GEMM + k0 + kk];
            As[kk + 0][m] = v.x;
            As[kk + 1][m] = v.y;
            As[kk + 2][m] = v.z;
            As[kk + 3][m] = v.w;
        }
        // load B tile: 16x128 floats = 512 float4; 2 per thread
        #pragma unroll
        for (int l = 0; l < 2; l++) {
            int f  = tid + l * 256;
            int kk = f >> 5;            // 0..15
            int n4 = (f & 31) * 4;
            *(float4*)&Bs[kk][n4] =
                *(const float4*)&W[(size_t)(k0 + kk) * D_OUT + n4];
        }
        __syncthreads();

        #pragma unroll
        for (int kk = 0; kk < BK; kk++) {
            float a[8], b[8];
            *(float4*)(a)     = *(const float4*)&As[kk][ty * 8];
            *(float4*)(a + 4) = *(const float4*)&As[kk][ty * 8 + 4];
            *(float4*)(b)     = *(const float4*)&Bs[kk][tx * 8];
            *(float4*)(b + 4) = *(const float4*)&Bs[kk][tx * 8 + 4];
            #pragma unroll
            for (int i = 0; i < 8; i++)
                #pragma unroll
                for (int j = 0; j < 8; j++)
                    acc[i][j] = fmaf(a[i], b[j], acc[i][j]);
        }
        __syncthreads();
    }

    // epilogue: add degree-embedding contribution, store
    #pragma unroll
    for (int i = 0; i < 8; i++) {
        int row = bm + ty * 8 + i;
        if (row >= N_NODES) break;
        int dg = g_deg[row];
        const float* dw = &g_degW[dg * D_OUT];
        float o[8];
        #pragma unroll
        for (int j = 0; j < 8; j++)
            o[j] = acc[i][j] + dw[tx * 8 + j];
        *(float4*)&out[(size_t)row * D_OUT + tx * 8]     = *(float4*)(o);
        *(float4*)&out[(size_t)row * D_OUT + tx * 8 + 4] = *(float4*)(o + 4);
    }
}

// ------------------------- batchnorm stats --------------------------------
__global__ void k_bnstats(const float* __restrict__ h) {
    int c = threadIdx.x;   // 0..127
    float s = 0.f, sq = 0.f;
    for (int r = blockIdx.x; r < N_NODES; r += gridDim.x) {
        float v = h[(size_t)r * D_OUT + c];
        s += v;
        sq = fmaf(v, v, sq);
    }
    atomicAdd(&g_colsum[c], s);
    atomicAdd(&g_colsq[c], sq);
}

__global__ void k_bnfinal(const float* __restrict__ gamma,
                          const float* __restrict__ beta) {
    int c = threadIdx.x;
    float inv_n = 1.f / (float)N_NODES;
    float mu  = g_colsum[c] * inv_n;
    float var = g_colsq[c] * inv_n - mu * mu;
    float rstd = rsqrtf(var + EPS_BN);
    float sc = gamma[c] * rstd;
    g_scale[c] = sc;
    g_bias[c]  = beta[c] - mu * sc;
}

__global__ void k_normalize(float* __restrict__ out) {
    int i = blockIdx.x * blockDim.x + threadIdx.x;
    if (i < N_NODES * D_OUT) {
        int c = i & (D_OUT - 1);
        out[i] = fmaxf(0.f, fmaf(out[i], g_scale[c], g_bias[c]));
    }
}

// ------------------------- launch -----------------------------------------
extern "C" void kernel_launch(void* const* d_in, const int* in_sizes, int n_in,
                              void* d_out, int out_size) {
    const float* inputs  = (const float*)d_in[0];   // [E, 128]
    const int*   index   = (const int*)  d_in[1];   // [E]
    const float* deg_emb = (const float*)d_in[2];   // [100, 128]
    const float* W       = (const float*)d_in[3];   // [640, 128]
    const float* gamma   = (const float*)d_in[4];   // [128]
    const float* beta    = (const float*)d_in[5];   // [128]
    float* out = (float*)d_out;                     // [50000, 128]

    k_zeroinit<<<(N_NODES + 255) / 256, 256>>>();
    k_hist<<<(E_EDGES + 255) / 256, 256>>>(index);
    k_scan1<<<SCAN_NBLK, SCAN_BLK>>>();
    k_scan2<<<1, SCAN_BLK>>>();
    k_scan3<<<SCAN_NBLK, SCAN_BLK>>>();
    k_scatter<<<(E_EDGES + 255) / 256, 256>>>(index);
    k_agg<<<N_NODES, 128>>>(inputs);
    k_degw<<<100, 128>>>(deg_emb, W);
    k_gemm<<<(N_NODES + BM - 1) / BM, 256>>>(W, out);
    k_bnstats<<<256, 128>>>(out);
    k_bnfinal<<<1, 128>>>(gamma, beta);
    k_normalize<<<(N_NODES * D_OUT + 255) / 256, 256>>>(out);
}

// round 3
// speedup vs baseline: 1.2702x; 1.2702x over previous
#include <cuda_runtime.h>
#include <cuda_bf16.h>
#include <math.h>
#include <float.h>
#include <stdint.h>

// Problem constants (fixed by dataset)
#define E_EDGES   1600000
#define N_NODES   50000
#define D_IN      128
#define D_OUT     128
#define K_GEMM    512          // 4 stats * 128
#define EPS_STD   1e-5f
#define EPS_BN    1e-5f

#define SCAN_BLK  256
#define SCAN_NBLK ((N_NODES + SCAN_BLK - 1) / SCAN_BLK)   // 196
#define GEMM_TILES ((N_NODES + 127) / 128)                // 391

// ------------------------- device scratch --------------------------------
__device__ int   g_counts[N_NODES];
__device__ int   g_offsets[N_NODES + 1];
__device__ int   g_cursor[N_NODES];
__device__ int   g_deg[N_NODES];
__device__ int   g_perm[E_EDGES];
__device__ int   g_blocksums[SCAN_NBLK];
__device__ __nv_bfloat16 g_xhi[(size_t)N_NODES * K_GEMM]; // aggregated feats hi
__device__ __nv_bfloat16 g_xlo[(size_t)N_NODES * K_GEMM]; // aggregated feats lo
__device__ __nv_bfloat16 g_wt_hi[D_OUT * K_GEMM];         // W[0:512]^T hi  [n][k]
__device__ __nv_bfloat16 g_wt_lo[D_OUT * K_GEMM];         // W[0:512]^T lo  [n][k]
__device__ float g_degW[100 * D_OUT];                     // deg_emb @ W[512:640]
__device__ float g_colsum[D_OUT];
__device__ float g_colsq[D_OUT];
__device__ float g_scale[D_OUT];
__device__ float g_bias[D_OUT];

// ------------------------- init ------------------------------------------
__global__ void k_zeroinit() {
    int i = blockIdx.x * blockDim.x + threadIdx.x;
    if (i < N_NODES) g_counts[i] = 0;
    if (i < D_OUT) { g_colsum[i] = 0.f; g_colsq[i] = 0.f; }
}

// ------------------------- histogram -------------------------------------
__global__ void k_hist(const int* __restrict__ index) {
    int i = blockIdx.x * blockDim.x + threadIdx.x;
    if (i < E_EDGES) atomicAdd(&g_counts[index[i]], 1);
}

// ------------------------- scan (3 phases) --------------------------------
__global__ void k_scan1() {
    __shared__ int sm[SCAN_BLK];
    int i = blockIdx.x * SCAN_BLK + threadIdx.x;
    sm[threadIdx.x] = (i < N_NODES) ? g_counts[i] : 0;
    __syncthreads();
    for (int off = SCAN_BLK / 2; off > 0; off >>= 1) {
        if (threadIdx.x < off) sm[threadIdx.x] += sm[threadIdx.x + off];
        __syncthreads();
    }
    if (threadIdx.x == 0) g_blocksums[blockIdx.x] = sm[0];
}

__global__ void k_scan2() {
    __shared__ int sm[2][SCAN_BLK];
    int t = threadIdx.x;
    int v = (t < SCAN_NBLK) ? g_blocksums[t] : 0;
    sm[0][t] = v;
    __syncthreads();
    int pin = 0;
    for (int off = 1; off < SCAN_BLK; off <<= 1) {
        int nv = sm[pin][t] + ((t >= off) ? sm[pin][t - off] : 0);
        sm[pin ^ 1][t] = nv;
        __syncthreads();
        pin ^= 1;
    }
    if (t < SCAN_NBLK) g_blocksums[t] = sm[pin][t] - v;
}

__global__ void k_scan3() {
    __shared__ int sm[2][SCAN_BLK];
    int t = threadIdx.x;
    int i = blockIdx.x * SCAN_BLK + t;
    int v = (i < N_NODES) ? g_counts[i] : 0;
    sm[0][t] = v;
    __syncthreads();
    int pin = 0;
    for (int off = 1; off < SCAN_BLK; off <<= 1) {
        int nv = sm[pin][t] + ((t >= off) ? sm[pin][t - off] : 0);
        sm[pin ^ 1][t] = nv;
        __syncthreads();
        pin ^= 1;
    }
    int exc = sm[pin][t] - v;
    int base = g_blocksums[blockIdx.x];
    if (i < N_NODES) {
        g_offsets[i] = base + exc;
        g_cursor[i]  = base + exc;
    }
    if (i == 0) g_offsets[N_NODES] = E_EDGES;
}

// ------------------------- scatter ----------------------------------------
__global__ void k_scatter(const int* __restrict__ index) {
    int i = blockIdx.x * blockDim.x + threadIdx.x;
    if (i < E_EDGES) {
        int n = index[i];
        int p = atomicAdd(&g_cursor[n], 1);
        g_perm[p] = i;
    }
}

// ------------------------- per-node aggregation ---------------------------
__global__ __launch_bounds__(128) void k_agg(const float* __restrict__ inputs) {
    int n = blockIdx.x;
    int t = threadIdx.x;
    int start = g_offsets[n];
    int end   = g_offsets[n + 1];
    int cnt   = end - start;

    __shared__ int sperm[128];
    float s = 0.f, sq = 0.f;
    float mn = FLT_MAX, mx = -FLT_MAX;

    for (int base = start; base < end; base += 128) {
        int m = min(128, end - base);
        if (t < m) sperm[t] = g_perm[base + t];
        __syncthreads();
        #pragma unroll 4
        for (int j = 0; j < m; j++) {
            float v = __ldg(&inputs[(size_t)sperm[j] * D_IN + t]);
            s  += v;
            sq  = fmaf(v, v, sq);
            mn  = fminf(mn, v);
            mx  = fmaxf(mx, v);
        }
        __syncthreads();
    }

    float safe   = fmaxf((float)cnt, 1.f);
    float mean   = s / safe;
    float meansq = sq / safe;
    float stdv   = sqrtf(fmaxf(meansq - mean * mean, 0.f) + EPS_STD);
    if (cnt == 0) { mn = 0.f; mx = 0.f; }

    size_t rb = (size_t)n * K_GEMM;
    float vals[4] = { mean, mn, mx, stdv };
    #pragma unroll
    for (int q = 0; q < 4; q++) {
        float v = vals[q];
        __nv_bfloat16 hi = __float2bfloat16(v);
        float lo = v - __bfloat162float(hi);
        g_xhi[rb + q * 128 + t] = hi;
        g_xlo[rb + q * 128 + t] = __float2bfloat16(lo);
    }
    if (t == 0) g_deg[n] = min(cnt, 99);
}

// ------------------------- degW = deg_emb @ W[512:640] (exact fp32) -------
__global__ void k_degw(const float* __restrict__ deg_emb, const float* __restrict__ W) {
    int d = blockIdx.x;
    int o = threadIdx.x;
    __shared__ float e[D_IN];
    e[o] = deg_emb[d * D_IN + o];
    __syncthreads();
    float acc = 0.f;
    #pragma unroll 8
    for (int k = 0; k < D_IN; k++)
        acc = fmaf(e[k], W[(size_t)(K_GEMM + k) * D_OUT + o], acc);
    g_degW[d * D_OUT + o] = acc;
}

// ------------------------- W transpose + bf16 split ------------------------
__global__ void k_wprep(const float* __restrict__ W) {
    int n = blockIdx.x;      // 0..127
    int t = threadIdx.x;     // 0..127
    #pragma unroll
    for (int q = 0; q < 4; q++) {
        int k = q * 128 + t;
        float v = W[(size_t)k * D_OUT + n];
        __nv_bfloat16 hi = __float2bfloat16(v);
        float lo = v - __bfloat162float(hi);
        g_wt_hi[(size_t)n * K_GEMM + k] = hi;
        g_wt_lo[(size_t)n * K_GEMM + k] = __float2bfloat16(lo);
    }
}

// ------------------------- tensor-core GEMM (mma.sync bf16, 3-term) -------
// h[50000,128] = Xhi@Whi^T + Xhi@Wlo^T + Xlo@Whi^T  (+ degW epilogue)
// CTA tile M=128, N=128; K chunks of 64; 8 warps (2 rows x 4 cols), warp 64x32.
#define BK      64
#define APITCH  72          // bf16 elements per smem row (64 + 8 pad)
#define SM_TILE (128 * APITCH * 2)          // 18432 bytes per tile
#define SM_AHI  0
#define SM_ALO  (SM_TILE)
#define SM_BHI  (2 * SM_TILE)
#define SM_BLO  (3 * SM_TILE)
#define SM_GEMM_TOTAL (4 * SM_TILE)         // 73728 bytes

__device__ __forceinline__ uint32_t smem_u32(const void* p) {
    uint32_t a;
    asm("{ .reg .u64 t; cvta.to.shared.u64 t, %1; cvt.u32.u64 %0, t; }" : "=r"(a) : "l"(p));
    return a;
}
__device__ __forceinline__ void ldm_x4(uint32_t& r0, uint32_t& r1, uint32_t& r2, uint32_t& r3,
                                       uint32_t addr) {
    asm volatile("ldmatrix.sync.aligned.m8n8.x4.shared.b16 {%0,%1,%2,%3}, [%4];"
                 : "=r"(r0), "=r"(r1), "=r"(r2), "=r"(r3) : "r"(addr));
}
__device__ __forceinline__ void ldm_x2(uint32_t& r0, uint32_t& r1, uint32_t addr) {
    asm volatile("ldmatrix.sync.aligned.m8n8.x2.shared.b16 {%0,%1}, [%2];"
                 : "=r"(r0), "=r"(r1) : "r"(addr));
}
__device__ __forceinline__ void mma_bf16(float* c, uint32_t a0, uint32_t a1, uint32_t a2,
                                         uint32_t a3, uint32_t b0, uint32_t b1) {
    asm volatile(
        "mma.sync.aligned.m16n8k16.row.col.f32.bf16.bf16.f32 "
        "{%0,%1,%2,%3}, {%4,%5,%6,%7}, {%8,%9}, {%0,%1,%2,%3};"
        : "+f"(c[0]), "+f"(c[1]), "+f"(c[2]), "+f"(c[3])
        : "r"(a0), "r"(a1), "r"(a2), "r"(a3), "r"(b0), "r"(b1));
}

__global__ __launch_bounds__(256) void k_gemm_mma(float* __restrict__ out) {
    extern __shared__ char smem[];
    uint32_t sbase = smem_u32(smem);

    int t    = threadIdx.x;
    int wid  = t >> 5;
    int lane = t & 31;
    int warp_m = wid >> 2;              // 0..1 -> 64 rows each
    int warp_n = wid & 3;               // 0..3 -> 32 cols each
    int bm = blockIdx.x * 128;

    float acc[4][4][4];                 // [mi][nj][4]
    #pragma unroll
    for (int i = 0; i < 4; i++)
        #pragma unroll
        for (int j = 0; j < 4; j++)
            #pragma unroll
            for (int q = 0; q < 4; q++) acc[i][j][q] = 0.f;

    // ldmatrix smem addresses (fixed per thread, advance by k within chunk)
    int a_row = warp_m * 64 + (lane & 15);      // + mi*16
    int a_kof = (lane >> 4) * 8;                // + ks*16
    int b_row = warp_n * 32 + (lane & 7);       // + nj*8
    int b_kof = ((lane >> 3) & 1) * 8;          // + ks*16  (lanes 0-15 matter)

    for (int c = 0; c < K_GEMM / BK; c++) {
        // ---- load 4 tiles gmem -> smem (each thread: 4 uint4 per tile) ----
        __syncthreads();
        #pragma unroll
        for (int l = 0; l < 4; l++) {
            int idx  = t + l * 256;             // 0..1023
            int row  = idx >> 3;                // 0..127
            int col8 = idx & 7;                 // 16B unit within 128B chunk
            size_t gofs = (size_t)row * K_GEMM + c * BK + col8 * 8;
            uint32_t sofs = (uint32_t)row * (APITCH * 2) + col8 * 16;
            int grow = bm + row;
            uint4 vh = make_uint4(0, 0, 0, 0), vl = make_uint4(0, 0, 0, 0);
            if (grow < N_NODES) {
                vh = *(const uint4*)(g_xhi + (size_t)bm * K_GEMM + gofs);
                vl = *(const uint4*)(g_xlo + (size_t)bm * K_GEMM + gofs);
            }
            *(uint4*)(smem + SM_AHI + sofs) = vh;
            *(uint4*)(smem + SM_ALO + sofs) = vl;
            *(uint4*)(smem + SM_BHI + sofs) = *(const uint4*)(g_wt_hi + gofs);
            *(uint4*)(smem + SM_BLO + sofs) = *(const uint4*)(g_wt_lo + gofs);
        }
        __syncthreads();

        #pragma unroll
        for (int ks = 0; ks < BK / 16; ks++) {
            // B fragments for this k-step (4 nj, hi+lo)
            uint32_t bh[4][2], bl[4][2];
            #pragma unroll
            for (int nj = 0; nj < 4; nj++) {
                uint32_t bofs = (uint32_t)(b_row + nj * 8) * (APITCH * 2)
                              + (ks * 16 + b_kof) * 2;
                ldm_x2(bh[nj][0], bh[nj][1], sbase + SM_BHI + bofs);
                ldm_x2(bl[nj][0], bl[nj][1], sbase + SM_BLO + bofs);
            }
            #pragma unroll
            for (int mi = 0; mi < 4; mi++) {
                uint32_t aofs = (uint32_t)(a_row + mi * 16) * (APITCH * 2)
                              + (ks * 16 + a_kof) * 2;
                uint32_t ah0, ah1, ah2, ah3, al0, al1, al2, al3;
                ldm_x4(ah0, ah1, ah2, ah3, sbase + SM_AHI + aofs);
                ldm_x4(al0, al1, al2, al3, sbase + SM_ALO + aofs);
                #pragma unroll
                for (int nj = 0; nj < 4; nj++) {
                    mma_bf16(acc[mi][nj], ah0, ah1, ah2, ah3, bh[nj][0], bh[nj][1]);
                    mma_bf16(acc[mi][nj], ah0, ah1, ah2, ah3, bl[nj][0], bl[nj][1]);
                    mma_bf16(acc[mi][nj], al0, al1, al2, al3, bh[nj][0], bh[nj][1]);
                }
            }
        }
    }

    // ---- epilogue: + degW[deg[row]], store fp32 ----
    int gid  = lane >> 2;       // 0..7
    int tig  = lane & 3;        // 0..3
    #pragma unroll
    for (int mi = 0; mi < 4; mi++) {
        #pragma unroll
        for (int half = 0; half < 2; half++) {
            int row = bm + warp_m * 64 + mi * 16 + gid + half * 8;
            if (row < N_NODES) {
                int dg = g_deg[row];
                const float* dw = &g_degW[dg * D_OUT];
                #pragma unroll
                for (int nj = 0; nj < 4; nj++) {
                    int col = warp_n * 32 + nj * 8 + tig * 2;
                    float2 v;
                    v.x = acc[mi][nj][half * 2 + 0] + dw[col];
                    v.y = acc[mi][nj][half * 2 + 1] + dw[col + 1];
                    *(float2*)&out[(size_t)row * D_OUT + col] = v;
                }
            }
        }
    }
}

// ------------------------- batchnorm --------------------------------------
__global__ void k_bnstats(const float* __restrict__ h) {
    int c = threadIdx.x;
    float s = 0.f, sq = 0.f;
    for (int r = blockIdx.x; r < N_NODES; r += gridDim.x) {
        float v = h[(size_t)r * D_OUT + c];
        s += v;
        sq = fmaf(v, v, sq);
    }
    atomicAdd(&g_colsum[c], s);
    atomicAdd(&g_colsq[c], sq);
}

__global__ void k_bnfinal(const float* __restrict__ gamma,
                          const float* __restrict__ beta) {
    int c = threadIdx.x;
    float inv_n = 1.f / (float)N_NODES;
    float mu  = g_colsum[c] * inv_n;
    float var = g_colsq[c] * inv_n - mu * mu;
    float rstd = rsqrtf(var + EPS_BN);
    float sc = gamma[c] * rstd;
    g_scale[c] = sc;
    g_bias[c]  = beta[c] - mu * sc;
}

__global__ void k_normalize(float* __restrict__ out) {
    int i = blockIdx.x * blockDim.x + threadIdx.x;
    if (i < N_NODES * D_OUT) {
        int c = i & (D_OUT - 1);
        out[i] = fmaxf(0.f, fmaf(out[i], g_scale[c], g_bias[c]));
    }
}

// ------------------------- launch -----------------------------------------
extern "C" void kernel_launch(void* const* d_in, const int* in_sizes, int n_in,
                              void* d_out, int out_size) {
    const float* inputs  = (const float*)d_in[0];   // [E, 128]
    const int*   index   = (const int*)  d_in[1];   // [E]
    const float* deg_emb = (const float*)d_in[2];   // [100, 128]
    const float* W       = (const float*)d_in[3];   // [640, 128]
    const float* gamma   = (const float*)d_in[4];   // [128]
    const float* beta    = (const float*)d_in[5];   // [128]
    float* out = (float*)d_out;                     // [50000, 128]

    cudaFuncSetAttribute(k_gemm_mma, cudaFuncAttributeMaxDynamicSharedMemorySize,
                         SM_GEMM_TOTAL);

    k_zeroinit<<<(N_NODES + 255) / 256, 256>>>();
    k_hist<<<(E_EDGES + 255) / 256, 256>>>(index);
    k_scan1<<<SCAN_NBLK, SCAN_BLK>>>();
    k_scan2<<<1, SCAN_BLK>>>();
    k_scan3<<<SCAN_NBLK, SCAN_BLK>>>();
    k_scatter<<<(E_EDGES + 255) / 256, 256>>>(index);
    k_agg<<<N_NODES, 128>>>(inputs);
    k_degw<<<100, 128>>>(deg_emb, W);
    k_wprep<<<128, 128>>>(W);
    k_gemm_mma<<<GEMM_TILES, 256, SM_GEMM_TOTAL>>>(out);
    k_bnstats<<<256, 128>>>(out);
    k_bnfinal<<<1, 128>>>(gamma, beta);
    k_normalize<<<(N_NODES * D_OUT + 255) / 256, 256>>>(out);
}

// round 4
// speedup vs baseline: 1.4805x; 1.1655x over previous
#include <cuda_runtime.h>
#include <cuda_bf16.h>
#include <math.h>
#include <float.h>
#include <stdint.h>

// Problem constants (fixed by dataset)
#define E_EDGES   1600000
#define N_NODES   50000
#define D_IN      128
#define D_OUT     128
#define K_GEMM    512          // 4 stats * 128
#define EPS_STD   1e-5f
#define EPS_BN    1e-5f

#define GEMM_TILES ((N_NODES + 127) / 128)                // 391

// ------------------------- device scratch --------------------------------
__device__ int   g_counts[N_NODES];
__device__ int   g_offsets[N_NODES + 1];
__device__ int   g_cursor[N_NODES];
__device__ int   g_deg[N_NODES];
__device__ int   g_perm[E_EDGES];
__device__ __nv_bfloat16 g_xhi[(size_t)N_NODES * K_GEMM];
__device__ __nv_bfloat16 g_xlo[(size_t)N_NODES * K_GEMM];
__device__ __nv_bfloat16 g_wt_hi[D_OUT * K_GEMM];         // W[0:512]^T hi  [n][k]
__device__ __nv_bfloat16 g_wt_lo[D_OUT * K_GEMM];         // W[0:512]^T lo  [n][k]
__device__ float g_degW[100 * D_OUT];                     // deg_emb @ W[512:640]
__device__ float g_colsum[D_OUT];
__device__ float g_colsq[D_OUT];
__device__ float g_scale[D_OUT];
__device__ float g_bias[D_OUT];

// ------------------------- init ------------------------------------------
__global__ void k_zeroinit() {
    int i = blockIdx.x * blockDim.x + threadIdx.x;
    if (i < N_NODES) g_counts[i] = 0;
    if (i < D_OUT) { g_colsum[i] = 0.f; g_colsq[i] = 0.f; }
}

// ------------------------- histogram -------------------------------------
__global__ void k_hist(const int* __restrict__ index) {
    int i = blockIdx.x * blockDim.x + threadIdx.x;
    if (i < E_EDGES) atomicAdd(&g_counts[index[i]], 1);
}

// ------------------------- single-kernel scan ------------------------------
__global__ __launch_bounds__(1024) void k_scan_all() {
    __shared__ int wsum[32];
    __shared__ int s_carry;
    int t = threadIdx.x;
    int lane = t & 31, w = t >> 5;
    if (t == 0) s_carry = 0;
    __syncthreads();
    for (int base = 0; base < N_NODES; base += 1024) {
        int idx = base + t;
        int v = (idx < N_NODES) ? g_counts[idx] : 0;
        int x = v;
        #pragma unroll
        for (int o = 1; o < 32; o <<= 1) {
            int y = __shfl_up_sync(0xffffffffu, x, o);
            if (lane >= o) x += y;
        }
        if (lane == 31) wsum[w] = x;
        __syncthreads();
        if (w == 0) {
            int y = wsum[lane];
            #pragma unroll
            for (int o = 1; o < 32; o <<= 1) {
                int z = __shfl_up_sync(0xffffffffu, y, o);
                if (lane >= o) y += z;
            }
            wsum[lane] = y;
        }
        __syncthreads();
        int warp_prefix = (w == 0) ? 0 : wsum[w - 1];
        int incl = x + warp_prefix;
        int excl = incl - v + s_carry;
        if (idx < N_NODES) { g_offsets[idx] = excl; g_cursor[idx] = excl; }
        __syncthreads();
        if (t == 1023) s_carry += incl;
        __syncthreads();
    }
    if (t == 0) g_offsets[N_NODES] = E_EDGES;
}

// ------------------------- scatter ----------------------------------------
__global__ void k_scatter(const int* __restrict__ index) {
    int i = blockIdx.x * blockDim.x + threadIdx.x;
    if (i < E_EDGES) {
        int n = index[i];
        int p = atomicAdd(&g_cursor[n], 1);
        g_perm[p] = i;
    }
}

// ------------------------- per-node aggregation ---------------------------
// 4 warps per node; warp w handles edges j==w (mod 4); lane owns dims [4l..4l+3]
__global__ __launch_bounds__(128) void k_agg(const float* __restrict__ inputs) {
    int n = blockIdx.x;
    int t = threadIdx.x;
    int w = t >> 5, lane = t & 31;
    int start = g_offsets[n];
    int end   = g_offsets[n + 1];
    int cnt   = end - start;

    __shared__ int sperm[128];
    __shared__ float red[4][4][128];   // [stat][warp][dim]

    float4 s  = make_float4(0.f, 0.f, 0.f, 0.f);
    float4 sq = make_float4(0.f, 0.f, 0.f, 0.f);
    float4 mn = make_float4(FLT_MAX, FLT_MAX, FLT_MAX, FLT_MAX);
    float4 mx = make_float4(-FLT_MAX, -FLT_MAX, -FLT_MAX, -FLT_MAX);

    for (int base = start; base < end; base += 128) {
        int m = min(128, end - base);
        if (t < m) sperm[t] = g_perm[base + t];
        __syncthreads();
        for (int j = w; j < m; j += 4) {
            const float4 v = __ldg((const float4*)(inputs + (size_t)sperm[j] * D_IN + lane * 4));
            s.x += v.x;  s.y += v.y;  s.z += v.z;  s.w += v.w;
            sq.x = fmaf(v.x, v.x, sq.x); sq.y = fmaf(v.y, v.y, sq.y);
            sq.z = fmaf(v.z, v.z, sq.z); sq.w = fmaf(v.w, v.w, sq.w);
            mn.x = fminf(mn.x, v.x); mn.y = fminf(mn.y, v.y);
            mn.z = fminf(mn.z, v.z); mn.w = fminf(mn.w, v.w);
            mx.x = fmaxf(mx.x, v.x); mx.y = fmaxf(mx.y, v.y);
            mx.z = fmaxf(mx.z, v.z); mx.w = fmaxf(mx.w, v.w);
        }
        __syncthreads();
    }

    *(float4*)&red[0][w][lane * 4] = s;
    *(float4*)&red[1][w][lane * 4] = sq;
    *(float4*)&red[2][w][lane * 4] = mn;
    *(float4*)&red[3][w][lane * 4] = mx;
    __syncthreads();

    float S = 0.f, SQ = 0.f, MN = FLT_MAX, MX = -FLT_MAX;
    #pragma unroll
    for (int w2 = 0; w2 < 4; w2++) {
        S  += red[0][w2][t];
        SQ += red[1][w2][t];
        MN  = fminf(MN, red[2][w2][t]);
        MX  = fmaxf(MX, red[3][w2][t]);
    }

    float safe   = fmaxf((float)cnt, 1.f);
    float mean   = S / safe;
    float meansq = SQ / safe;
    float stdv   = sqrtf(fmaxf(meansq - mean * mean, 0.f) + EPS_STD);
    if (cnt == 0) { MN = 0.f; MX = 0.f; }

    size_t rb = (size_t)n * K_GEMM;
    float vals[4] = { mean, MN, MX, stdv };
    #pragma unroll
    for (int q = 0; q < 4; q++) {
        float v = vals[q];
        __nv_bfloat16 hi = __float2bfloat16(v);
        float lo = v - __bfloat162float(hi);
        g_xhi[rb + q * 128 + t] = hi;
        g_xlo[rb + q * 128 + t] = __float2bfloat16(lo);
    }
    if (t == 0) g_deg[n] = min(cnt, 99);
}

// ------------------------- degW = deg_emb @ W[512:640] (exact fp32) -------
__global__ void k_degw(const float* __restrict__ deg_emb, const float* __restrict__ W) {
    int d = blockIdx.x;
    int o = threadIdx.x;
    __shared__ float e[D_IN];
    e[o] = deg_emb[d * D_IN + o];
    __syncthreads();
    float acc = 0.f;
    #pragma unroll 8
    for (int k = 0; k < D_IN; k++)
        acc = fmaf(e[k], W[(size_t)(K_GEMM + k) * D_OUT + o], acc);
    g_degW[d * D_OUT + o] = acc;
}

// ------------------------- W transpose + bf16 split ------------------------
__global__ void k_wprep(const float* __restrict__ W) {
    int n = blockIdx.x;
    int t = threadIdx.x;
    #pragma unroll
    for (int q = 0; q < 4; q++) {
        int k = q * 128 + t;
        float v = W[(size_t)k * D_OUT + n];
        __nv_bfloat16 hi = __float2bfloat16(v);
        float lo = v - __bfloat162float(hi);
        g_wt_hi[(size_t)n * K_GEMM + k] = hi;
        g_wt_lo[(size_t)n * K_GEMM + k] = __float2bfloat16(lo);
    }
}

// ------------------------- tensor-core GEMM (mma.sync, cp.async pipeline) --
// h = Xhi@Whi^T + Xhi@Wlo^T + Xlo@Whi^T (+ degW); BN col-stats fused.
#define GBK     32
#define GAPITCH 40                          // bf16 elems per smem row (32+8 pad)
#define TILE_B  (128 * GAPITCH * 2)         // 10240 bytes
#define STAGE_B (4 * TILE_B)                // Ahi|Alo|Bhi|Blo = 40960
#define SM_GEMM_TOTAL (2 * STAGE_B)         // 81920
#define NCHUNK  (K_GEMM / GBK)              // 16

__device__ __forceinline__ uint32_t smem_u32(const void* p) {
    uint32_t a;
    asm("{ .reg .u64 t; cvta.to.shared.u64 t, %1; cvt.u32.u64 %0, t; }" : "=r"(a) : "l"(p));
    return a;
}
__device__ __forceinline__ void cp16(uint32_t dst, const void* src, int ok) {
    asm volatile("cp.async.cg.shared.global [%0], [%1], 16, %2;"
                 :: "r"(dst), "l"(src), "r"(ok ? 16 : 0) : "memory");
}
__device__ __forceinline__ void ldm_x4(uint32_t& r0, uint32_t& r1, uint32_t& r2, uint32_t& r3,
                                       uint32_t addr) {
    asm volatile("ldmatrix.sync.aligned.m8n8.x4.shared.b16 {%0,%1,%2,%3}, [%4];"
                 : "=r"(r0), "=r"(r1), "=r"(r2), "=r"(r3) : "r"(addr));
}
__device__ __forceinline__ void ldm_x2(uint32_t& r0, uint32_t& r1, uint32_t addr) {
    asm volatile("ldmatrix.sync.aligned.m8n8.x2.shared.b16 {%0,%1}, [%2];"
                 : "=r"(r0), "=r"(r1) : "r"(addr));
}
__device__ __forceinline__ void mma_bf16(float* c, uint32_t a0, uint32_t a1, uint32_t a2,
                                         uint32_t a3, uint32_t b0, uint32_t b1) {
    asm volatile(
        "mma.sync.aligned.m16n8k16.row.col.f32.bf16.bf16.f32 "
        "{%0,%1,%2,%3}, {%4,%5,%6,%7}, {%8,%9}, {%0,%1,%2,%3};"
        : "+f"(c[0]), "+f"(c[1]), "+f"(c[2]), "+f"(c[3])
        : "r"(a0), "r"(a1), "r"(a2), "r"(a3), "r"(b0), "r"(b1));
}

__global__ __launch_bounds__(256, 2) void k_gemm_mma(float* __restrict__ out) {
    extern __shared__ char smem[];
    uint32_t sbase = smem_u32(smem);

    int t    = threadIdx.x;
    int wid  = t >> 5;
    int lane = t & 31;
    int warp_m = wid >> 2;              // 0..1 (64 rows)
    int warp_n = wid & 3;               // 0..3 (32 cols)
    int bm = blockIdx.x * 128;

    float acc[4][4][4];
    #pragma unroll
    for (int i = 0; i < 4; i++)
        #pragma unroll
        for (int j = 0; j < 4; j++)
            #pragma unroll
            for (int q = 0; q < 4; q++) acc[i][j][q] = 0.f;

    int a_row = warp_m * 64 + (lane & 15);
    int a_kof = (lane >> 4) * 8;
    int b_row = warp_n * 32 + (lane & 7);
    int b_kof = ((lane >> 3) & 1) * 8;

    const char* xhi = (const char*)(g_xhi + (size_t)bm * K_GEMM);
    const char* xlo = (const char*)(g_xlo + (size_t)bm * K_GEMM);

    // issue loads for chunk c into stage st
    int r0 = t >> 2, u0 = t & 3;                  // pass 0: rows 0..63
    int r1 = (t + 256) >> 2, u1 = t & 3;          // pass 1: rows 64..127
    int okA0 = (bm + r0) < N_NODES;
    int okA1 = (bm + r1) < N_NODES;

    #define ISSUE(c, st) do {                                                   \
        uint32_t sbuf = sbase + (st) * STAGE_B;                                  \
        size_t go0 = ((size_t)r0 * K_GEMM + (c) * GBK + u0 * 8) * 2;             \
        size_t go1 = ((size_t)r1 * K_GEMM + (c) * GBK + u1 * 8) * 2;             \
        uint32_t so0 = (uint32_t)r0 * (GAPITCH * 2) + u0 * 16;                   \
        uint32_t so1 = (uint32_t)r1 * (GAPITCH * 2) + u1 * 16;                   \
        cp16(sbuf + 0 * TILE_B + so0, xhi + go0, okA0);                          \
        cp16(sbuf + 1 * TILE_B + so0, xlo + go0, okA0);                          \
        cp16(sbuf + 2 * TILE_B + so0, (const char*)g_wt_hi + go0, 1);            \
        cp16(sbuf + 3 * TILE_B + so0, (const char*)g_wt_lo + go0, 1);            \
        cp16(sbuf + 0 * TILE_B + so1, xhi + go1, okA1);                          \
        cp16(sbuf + 1 * TILE_B + so1, xlo + go1, okA1);                          \
        cp16(sbuf + 2 * TILE_B + so1, (const char*)g_wt_hi + go1, 1);            \
        cp16(sbuf + 3 * TILE_B + so1, (const char*)g_wt_lo + go1, 1);            \
        asm volatile("cp.async.commit_group;" ::: "memory");                     \
    } while (0)

    ISSUE(0, 0);

    for (int c = 0; c < NCHUNK; c++) {
        int st = c & 1;
        if (c + 1 < NCHUNK) {
            ISSUE(c + 1, st ^ 1);
            asm volatile("cp.async.wait_group 1;" ::: "memory");
        } else {
            asm volatile("cp.async.wait_group 0;" ::: "memory");
        }
        __syncthreads();

        uint32_t sb = sbase + st * STAGE_B;
        #pragma unroll
        for (int ks = 0; ks < GBK / 16; ks++) {
            uint32_t bh[4][2], bl[4][2];
            #pragma unroll
            for (int nj = 0; nj < 4; nj++) {
                uint32_t bofs = (uint32_t)(b_row + nj * 8) * (GAPITCH * 2)
                              + (ks * 16 + b_kof) * 2;
                ldm_x2(bh[nj][0], bh[nj][1], sb + 2 * TILE_B + bofs);
                ldm_x2(bl[nj][0], bl[nj][1], sb + 3 * TILE_B + bofs);
            }
            #pragma unroll
            for (int mi = 0; mi < 4; mi++) {
                uint32_t aofs = (uint32_t)(a_row + mi * 16) * (GAPITCH * 2)
                              + (ks * 16 + a_kof) * 2;
                uint32_t ah0, ah1, ah2, ah3, al0, al1, al2, al3;
                ldm_x4(ah0, ah1, ah2, ah3, sb + 0 * TILE_B + aofs);
                ldm_x4(al0, al1, al2, al3, sb + 1 * TILE_B + aofs);
                #pragma unroll
                for (int nj = 0; nj < 4; nj++) {
                    mma_bf16(acc[mi][nj], ah0, ah1, ah2, ah3, bh[nj][0], bh[nj][1]);
                    mma_bf16(acc[mi][nj], ah0, ah1, ah2, ah3, bl[nj][0], bl[nj][1]);
                    mma_bf16(acc[mi][nj], al0, al1, al2, al3, bh[nj][0], bh[nj][1]);
                }
            }
        }
        __syncthreads();
    }

    // ---- epilogue: + degW, store, BN column partials ----
    float* scol  = (float*)smem;          // 128 floats
    float* scolq = (float*)(smem + 512);  // 128 floats
    if (t < 128) { scol[t] = 0.f; scolq[t] = 0.f; }
    __syncthreads();

    int gid = lane >> 2;
    int tig = lane & 3;
    float ls[8], lq[8];
    #pragma unroll
    for (int q = 0; q < 8; q++) { ls[q] = 0.f; lq[q] = 0.f; }

    #pragma unroll
    for (int mi = 0; mi < 4; mi++) {
        #pragma unroll
        for (int half = 0; half < 2; half++) {
            int row = bm + warp_m * 64 + mi * 16 + gid + half * 8;
            if (row < N_NODES) {
                int dg = g_deg[row];
                const float* dw = &g_degW[dg * D_OUT];
                #pragma unroll
                for (int nj = 0; nj < 4; nj++) {
                    int col = warp_n * 32 + nj * 8 + tig * 2;
                    float2 v;
                    v.x = acc[mi][nj][half * 2 + 0] + dw[col];
                    v.y = acc[mi][nj][half * 2 + 1] + dw[col + 1];
                    *(float2*)&out[(size_t)row * D_OUT + col] = v;
                    ls[nj * 2 + 0] += v.x;  lq[nj * 2 + 0] = fmaf(v.x, v.x, lq[nj * 2 + 0]);
                    ls[nj * 2 + 1] += v.y;  lq[nj * 2 + 1] = fmaf(v.y, v.y, lq[nj * 2 + 1]);
                }
            }
        }
    }
    #pragma unroll
    for (int nj = 0; nj < 4; nj++) {
        #pragma unroll
        for (int xy = 0; xy < 2; xy++) {
            int col = warp_n * 32 + nj * 8 + tig * 2 + xy;
            atomicAdd(&scol[col],  ls[nj * 2 + xy]);
            atomicAdd(&scolq[col], lq[nj * 2 + xy]);
        }
    }
    __syncthreads();
    if (t < 128) {
        atomicAdd(&g_colsum[t], scol[t]);
        atomicAdd(&g_colsq[t],  scolq[t]);
    }
}

// ------------------------- batchnorm finalize + normalize -----------------
__global__ void k_bnfinal(const float* __restrict__ gamma,
                          const float* __restrict__ beta) {
    int c = threadIdx.x;
    float inv_n = 1.f / (float)N_NODES;
    float mu  = g_colsum[c] * inv_n;
    float var = g_colsq[c] * inv_n - mu * mu;
    float rstd = rsqrtf(var + EPS_BN);
    float sc = gamma[c] * rstd;
    g_scale[c] = sc;
    g_bias[c]  = beta[c] - mu * sc;
}

__global__ void k_normalize(float* __restrict__ out) {
    int i = blockIdx.x * blockDim.x + threadIdx.x;   // float4 index
    if (i < N_NODES * D_OUT / 4) {
        int c0 = (i & 31) * 4;
        float4 v = ((float4*)out)[i];
        v.x = fmaxf(0.f, fmaf(v.x, g_scale[c0 + 0], g_bias[c0 + 0]));
        v.y = fmaxf(0.f, fmaf(v.y, g_scale[c0 + 1], g_bias[c0 + 1]));
        v.z = fmaxf(0.f, fmaf(v.z, g_scale[c0 + 2], g_bias[c0 + 2]));
        v.w = fmaxf(0.f, fmaf(v.w, g_scale[c0 + 3], g_bias[c0 + 3]));
        ((float4*)out)[i] = v;
    }
}

// ------------------------- launch -----------------------------------------
extern "C" void kernel_launch(void* const* d_in, const int* in_sizes, int n_in,
                              void* d_out, int out_size) {
    const float* inputs  = (const float*)d_in[0];   // [E, 128]
    const int*   index   = (const int*)  d_in[1];   // [E]
    const float* deg_emb = (const float*)d_in[2];   // [100, 128]
    const float* W       = (const float*)d_in[3];   // [640, 128]
    const float* gamma   = (const float*)d_in[4];   // [128]
    const float* beta    = (const float*)d_in[5];   // [128]
    float* out = (float*)d_out;                     // [50000, 128]

    cudaFuncSetAttribute(k_gemm_mma, cudaFuncAttributeMaxDynamicSharedMemorySize,
                         SM_GEMM_TOTAL);

    k_zeroinit<<<(N_NODES + 255) / 256, 256>>>();
    k_hist<<<(E_EDGES + 255) / 256, 256>>>(index);
    k_scan_all<<<1, 1024>>>();
    k_scatter<<<(E_EDGES + 255) / 256, 256>>>(index);
    k_agg<<<N_NODES, 128>>>(inputs);
    k_degw<<<100, 128>>>(deg_emb, W);
    k_wprep<<<128, 128>>>(W);
    k_gemm_mma<<<GEMM_TILES, 256, SM_GEMM_TOTAL>>>(out);
    k_bnfinal<<<1, 128>>>(gamma, beta);
    k_normalize<<<(N_NODES * D_OUT / 4 + 255) / 256, 256>>>(out);
}